// round 3
// baseline (speedup 1.0000x reference)
#include <cuda_runtime.h>
#include <cuda_bf16.h>
#include <math.h>

// ---------------- problem dims (fixed by the model) ----------------
#define N_MAX   100000
#define F_IN    28
#define G1      128     // conv1 out
#define G2      64      // conv2 out
#define L1      128     // dense1 out
#define L2      64      // dense2 out
#define PBLK    256     // product partial blocks

// ---------------- scratch (device globals: no allocation allowed) ----------------
__device__ __align__(16) float g_deg [N_MAX];
__device__ __align__(16) float g_dinv[N_MAX];
__device__ __align__(16) float g_h1  [(size_t)N_MAX * G1];   // x @ W1
__device__ __align__(16) float g_agg1[(size_t)N_MAX * G1];   // normalized aggregation layer 1
__device__ __align__(16) float g_h2  [(size_t)N_MAX * G2];   // tanh(a1) @ W2
__device__ __align__(16) float g_agg2[(size_t)N_MAX * G2];   // normalized aggregation layer 2
__device__ __align__(16) float g_part[PBLK * G2];            // product partials

// ---------------- degree ----------------
__global__ void deg_init_kernel(int n) {
    int i = blockIdx.x * blockDim.x + threadIdx.x;
    if (i < n) g_deg[i] = 1.0f;   // self loop
}

// edge_index is int32 [2, E] (JAX x64-disabled downcasts int64 -> int32)
__global__ void deg_count_kernel(const int* __restrict__ ei, int E) {
    int e = blockIdx.x * blockDim.x + threadIdx.x;
    if (e < E) {
        int c = ei[E + e];   // col
        atomicAdd(&g_deg[c], 1.0f);
    }
}

__global__ void dinv_kernel(int n) {
    int i = blockIdx.x * blockDim.x + threadIdx.x;
    if (i < n) g_dinv[i] = rsqrtf(g_deg[i]);  // deg >= 1 always
}

// ---------------- GEMM1: h1 = x @ W1 ; agg1 = h1 * dinv^2 (self-loop init) ----------------
// block: 128 threads (one per output feature), 32 nodes per block
__global__ void gemm1_kernel(const float* __restrict__ x,
                             const float* __restrict__ W1, int n) {
    __shared__ float Ws[F_IN * G1];     // 14 KB
    __shared__ float xs[32 * F_IN];     // 3.5 KB
    int f = threadIdx.x;
    for (int i = f; i < F_IN * G1; i += G1) Ws[i] = W1[i];

    int base = blockIdx.x * 32;
    int cnt  = min(32, n - base);
    for (int i = f; i < cnt * F_IN; i += G1) xs[i] = x[(size_t)base * F_IN + i];
    __syncthreads();

    for (int nn = 0; nn < cnt; nn++) {
        float acc = 0.f;
        #pragma unroll
        for (int k = 0; k < F_IN; k++)
            acc = fmaf(xs[nn * F_IN + k], Ws[k * G1 + f], acc);
        int node = base + nn;
        g_h1[(size_t)node * G1 + f] = acc;
        float di = g_dinv[node];
        g_agg1[(size_t)node * G1 + f] = acc * di * di;
    }
}

// ---------------- scatter layer 1: one warp per edge, float4 + red.v4 ----------------
__device__ __forceinline__ void red_add_v4(float* p, float4 v) {
    asm volatile("red.global.add.v4.f32 [%0], {%1, %2, %3, %4};"
                 :: "l"(p), "f"(v.x), "f"(v.y), "f"(v.z), "f"(v.w)
                 : "memory");
}

__global__ void scatter1_kernel(const int* __restrict__ ei, int E) {
    int warp = (blockIdx.x * blockDim.x + threadIdx.x) >> 5;
    int lane = threadIdx.x & 31;
    if (warp >= E) return;
    int r = ei[warp];
    int c = ei[E + warp];
    float norm = g_dinv[r] * g_dinv[c];
    float4 v = reinterpret_cast<const float4*>(g_h1 + (size_t)r * G1)[lane];
    v.x *= norm; v.y *= norm; v.z *= norm; v.w *= norm;
    red_add_v4(g_agg1 + (size_t)c * G1 + lane * 4, v);
}

// ---------------- GEMM2: a1 = tanh(agg1 + b1) (fused on load), h2 = a1 @ W2,
//                  agg2 = h2 * dinv^2 ----------------
// block: 256 threads = 64 features x 4 node-groups, 16 nodes per block
__global__ void gemm2_kernel(const float* __restrict__ W2,
                             const float* __restrict__ b1, int n) {
    __shared__ float Ws[G1 * G2];      // 32 KB
    __shared__ float as[16 * G1];      // 8 KB
    __shared__ float b1s[G1];
    int t = threadIdx.x;
    for (int i = t; i < G1 * G2; i += 256) Ws[i] = W2[i];
    if (t < G1) b1s[t] = b1[t];

    int base = blockIdx.x * 16;
    int cnt  = min(16, n - base);
    __syncthreads();
    for (int i = t; i < cnt * G1; i += 256)
        as[i] = tanhf(g_agg1[(size_t)base * G1 + i] + b1s[i & (G1 - 1)]);
    __syncthreads();

    int f = t & 63, ng = t >> 6;       // feature, node-group
    for (int nn = ng; nn < cnt; nn += 4) {
        float acc = 0.f;
        #pragma unroll
        for (int k = 0; k < G1; k++)
            acc = fmaf(as[nn * G1 + k], Ws[k * G2 + f], acc);
        int node = base + nn;
        g_h2[(size_t)node * G2 + f] = acc;
        float di = g_dinv[node];
        g_agg2[(size_t)node * G2 + f] = acc * di * di;
    }
}

// ---------------- scatter layer 2: 16 lanes per edge (64 floats = 16 x float4) ----------------
__global__ void scatter2_kernel(const int* __restrict__ ei, int E) {
    int tid  = blockIdx.x * blockDim.x + threadIdx.x;
    int edge = tid >> 4;
    int sub  = tid & 15;
    if (edge >= E) return;
    int r = ei[edge];
    int c = ei[E + edge];
    float norm = g_dinv[r] * g_dinv[c];
    float4 v = reinterpret_cast<const float4*>(g_h2 + (size_t)r * G2)[sub];
    v.x *= norm; v.y *= norm; v.z *= norm; v.w *= norm;
    red_add_v4(g_agg2 + (size_t)c * G2 + sub * 4, v);
}

// ---------------- product pooling partials: p_f = prod_i tanh(agg2[i,f] + b2[f]) ----------------
__global__ void prod_kernel(const float* __restrict__ b2, int n) {
    __shared__ float s[4][G2];
    int f   = threadIdx.x & 63;
    int grp = threadIdx.x >> 6;        // 0..3
    float b = b2[f];
    float p = 1.0f;
    for (int i = blockIdx.x * 4 + grp; i < n; i += gridDim.x * 4)
        p *= tanhf(g_agg2[(size_t)i * G2 + f] + b);
    s[grp][f] = p;
    __syncthreads();
    if (grp == 0)
        g_part[blockIdx.x * G2 + f] = s[0][f] * s[1][f] * s[2][f] * s[3][f];
}

// ---------------- final: finish product + dense head, single block of 128 ----------------
__global__ void head_kernel(const float* __restrict__ Wd1, const float* __restrict__ bd1,
                            const float* __restrict__ Wd2, const float* __restrict__ bd2,
                            const float* __restrict__ Wo,  const float* __restrict__ bo,
                            float* __restrict__ out, int out_size) {
    __shared__ float g0[G2];
    __shared__ float g1s[L1];
    __shared__ float g2s[L2];
    int t = threadIdx.x;

    if (t < G2) {
        float p = 1.0f;
        for (int b = 0; b < PBLK; b++) p *= g_part[b * G2 + t];
        g0[t] = p;
    }
    __syncthreads();

    // dense1: [64] @ [64,128] + b -> tanh
    {
        float acc = bd1[t];
        #pragma unroll
        for (int k = 0; k < G2; k++) acc = fmaf(g0[k], Wd1[k * L1 + t], acc);
        g1s[t] = tanhf(acc);
    }
    __syncthreads();

    // dense2: [128] @ [128,64] + b -> tanh ; this is g
    if (t < L2) {
        float acc = bd2[t];
        #pragma unroll
        for (int j = 0; j < L1; j++) acc = fmaf(g1s[j], Wd2[j * L2 + t], acc);
        float gv = tanhf(acc);
        g2s[t] = gv;
        if (1 + t < out_size) out[1 + t] = gv;   // g at [1..64]
    }
    __syncthreads();

    if (t == 0) {
        float acc = bo[0];
        #pragma unroll
        for (int f2 = 0; f2 < L2; f2++) acc = fmaf(g2s[f2], Wo[f2], acc);
        out[0] = acc;                            // scalar out at [0]
    }
}

// ---------------- launcher ----------------
extern "C" void kernel_launch(void* const* d_in, const int* in_sizes, int n_in,
                              void* d_out, int out_size) {
    const float* x   = (const float*)d_in[0];
    const int*   ei  = (const int*)d_in[1];     // int32 [2, E] (JAX x64 off)
    const float* W1  = (const float*)d_in[2];
    const float* b1  = (const float*)d_in[3];
    const float* W2  = (const float*)d_in[4];
    const float* b2  = (const float*)d_in[5];
    const float* Wd1 = (const float*)d_in[6];
    const float* bd1 = (const float*)d_in[7];
    const float* Wd2 = (const float*)d_in[8];
    const float* bd2 = (const float*)d_in[9];
    const float* Wo  = (const float*)d_in[10];
    const float* bo  = (const float*)d_in[11];
    float* out = (float*)d_out;

    int n = in_sizes[0] / F_IN;       // 100000
    int E = in_sizes[1] / 2;          // 1600000

    // 1-3: degree / normalization
    deg_init_kernel <<<(n + 255) / 256, 256>>>(n);
    deg_count_kernel<<<(E + 255) / 256, 256>>>(ei, E);
    dinv_kernel     <<<(n + 255) / 256, 256>>>(n);

    // 4: h1 = x@W1, agg1 init with self-loop term
    gemm1_kernel<<<(n + 31) / 32, G1>>>(x, W1, n);

    // 5: edge scatter layer 1 (1 warp / edge)
    {
        long long warps = E;
        int threads = 256;
        long long blocks = (warps * 32 + threads - 1) / threads;
        scatter1_kernel<<<(unsigned)blocks, threads>>>(ei, E);
    }

    // 6: tanh+bias fused + GEMM2 + self-loop init for agg2
    gemm2_kernel<<<(n + 15) / 16, 256>>>(W2, b1, n);

    // 7: edge scatter layer 2 (16 lanes / edge)
    {
        long long lanes = (long long)E * 16;
        int threads = 256;
        long long blocks = (lanes + threads - 1) / threads;
        scatter2_kernel<<<(unsigned)blocks, threads>>>(ei, E);
    }

    // 8: product pooling partials (tanh+bias fused on read)
    prod_kernel<<<PBLK, 256>>>(b2, n);

    // 9: finish product + dense head
    head_kernel<<<1, 128>>>(Wd1, bd1, Wd2, bd2, Wo, bo, out, out_size);
}

// round 4
// speedup vs baseline: 1.6006x; 1.6006x over previous
#include <cuda_runtime.h>
#include <cuda_bf16.h>
#include <math.h>

// ---------------- problem dims ----------------
#define N_MAX   100000
#define F_IN    28
#define XP      32      // padded input dim (float4 friendly)
#define G1      128
#define G2      64
#define L1      128
#define L2      64
#define PBLK    256
#define NB      64      // nodes per MLP block

// ---------------- scratch ----------------
__device__ __align__(16) float g_deg [N_MAX];
__device__ __align__(16) float g_dinv[N_MAX];
__device__ __align__(16) float g_x32 [(size_t)N_MAX * XP];   // x * dinv[row], padded to 32
__device__ __align__(16) float g_aggX[(size_t)N_MAX * XP];   // S @ x (28-dim aggregation)
__device__ __align__(16) float g_h2s [(size_t)N_MAX * G2];   // h2 * dinv[row]
__device__ __align__(16) float g_agg2[(size_t)N_MAX * G2];   // S @ h2
__device__ __align__(16) float g_part[PBLK * G2];

// ---------------- degree ----------------
__global__ void deg_init_kernel(int n) {
    int i = blockIdx.x * blockDim.x + threadIdx.x;
    if (i < n) g_deg[i] = 1.0f;   // self loop
}

__global__ void deg_count_kernel(const int* __restrict__ ei, int E) {
    int e = blockIdx.x * blockDim.x + threadIdx.x;
    if (e < E) atomicAdd(&g_deg[ei[E + e]], 1.0f);
}

// ---------------- prep: dinv + padded/prescaled x + aggX self-loop init ----------------
// one thread per (node, j) element, j in [0,32)
__global__ void prep_kernel(const float* __restrict__ x, int n) {
    int i = blockIdx.x * blockDim.x + threadIdx.x;
    if (i >= n * XP) return;
    int node = i >> 5, j = i & 31;
    float di = rsqrtf(g_deg[node]);
    if (j == 0) g_dinv[node] = di;
    float val = (j < F_IN) ? x[(size_t)node * F_IN + j] * di : 0.0f;
    g_x32 [i] = val;          // x * dinv[row]
    g_aggX[i] = val * di;     // self-loop: x * dinv^2
}

// ---------------- vector reduction helper ----------------
__device__ __forceinline__ void red_add_v4(float* p, float4 v) {
    asm volatile("red.global.add.v4.f32 [%0], {%1, %2, %3, %4};"
                 :: "l"(p), "f"(v.x), "f"(v.y), "f"(v.z), "f"(v.w)
                 : "memory");
}

// ---------------- scatter layer 1 in INPUT space: 8 lanes/edge x float4 ----------------
__global__ void scatter1_kernel(const int* __restrict__ ei, int E) {
    int tid = blockIdx.x * blockDim.x + threadIdx.x;
    int e = tid >> 3, sub = tid & 7;
    if (e >= E) return;
    int r = ei[e];
    int c = ei[E + e];
    float dc = g_dinv[c];
    float4 v = reinterpret_cast<const float4*>(g_x32 + (size_t)r * XP)[sub];
    v.x *= dc; v.y *= dc; v.z *= dc; v.w *= dc;
    red_add_v4(g_aggX + (size_t)c * XP + sub * 4, v);
}

// ---------------- fused MLP: t = tanh(aggX@W1 + b1); h2 = t@W2;
//                  g_h2s = h2*dinv; g_agg2 = h2*dinv^2 ----------------
// 256 threads, 64 nodes per block, dynamic smem 88.6 KB
__global__ void mlp_kernel(const float* __restrict__ W1, const float* __restrict__ b1,
                           const float* __restrict__ W2, int n) {
    extern __shared__ float sm[];
    float* Ws1 = sm;                  // 28*128 = 3584
    float* b1s = Ws1 + F_IN * G1;     // 128
    float* Ws2 = b1s + G1;            // 128*64 = 8192
    float* xs  = Ws2 + G1 * G2;       // 64*32  = 2048
    float* ts  = xs + NB * XP;        // 64*128 = 8192

    int t = threadIdx.x;
    for (int i = t; i < F_IN * G1; i += 256) Ws1[i] = W1[i];
    if (t < G1) b1s[t] = b1[t];
    for (int i = t; i < G1 * G2; i += 256) Ws2[i] = W2[i];

    int base = blockIdx.x * NB;
    int cnt  = min(NB, n - base);
    for (int i = t; i < cnt * XP; i += 256)
        xs[i] = g_aggX[(size_t)base * XP + i];
    __syncthreads();

    // stage 1: 128 features x 2 node groups
    {
        int f = t & 127, g = t >> 7;
        for (int nn = g; nn < cnt; nn += 2) {
            float acc = b1s[f];
            #pragma unroll
            for (int k = 0; k < F_IN; k++)
                acc = fmaf(xs[nn * XP + k], Ws1[k * G1 + f], acc);
            ts[nn * G1 + f] = tanhf(acc);
        }
    }
    __syncthreads();

    // stage 2: 64 features x 4 node groups
    {
        int f = t & 63, g = t >> 6;
        for (int nn = g; nn < cnt; nn += 4) {
            float acc = 0.f;
            #pragma unroll
            for (int k = 0; k < G1; k++)
                acc = fmaf(ts[nn * G1 + k], Ws2[k * G2 + f], acc);
            int node = base + nn;
            float di = g_dinv[node];
            float h2s = acc * di;
            g_h2s [(size_t)node * G2 + f] = h2s;       // pre-scaled by dinv[row]
            g_agg2[(size_t)node * G2 + f] = h2s * di;  // self-loop init
        }
    }
}

// ---------------- scatter layer 2: 16 lanes/edge x float4 ----------------
__global__ void scatter2_kernel(const int* __restrict__ ei, int E) {
    int tid  = blockIdx.x * blockDim.x + threadIdx.x;
    int e = tid >> 4, sub = tid & 15;
    if (e >= E) return;
    int r = ei[e];
    int c = ei[E + e];
    float dc = g_dinv[c];
    float4 v = reinterpret_cast<const float4*>(g_h2s + (size_t)r * G2)[sub];
    v.x *= dc; v.y *= dc; v.z *= dc; v.w *= dc;
    red_add_v4(g_agg2 + (size_t)c * G2 + sub * 4, v);
}

// ---------------- product pooling partials ----------------
__global__ void prod_kernel(const float* __restrict__ b2, int n) {
    __shared__ float s[4][G2];
    int f   = threadIdx.x & 63;
    int grp = threadIdx.x >> 6;
    float b = b2[f];
    float p = 1.0f;
    for (int i = blockIdx.x * 4 + grp; i < n; i += gridDim.x * 4)
        p *= tanhf(g_agg2[(size_t)i * G2 + f] + b);
    s[grp][f] = p;
    __syncthreads();
    if (grp == 0)
        g_part[blockIdx.x * G2 + f] = s[0][f] * s[1][f] * s[2][f] * s[3][f];
}

// ---------------- final head ----------------
__global__ void head_kernel(const float* __restrict__ Wd1, const float* __restrict__ bd1,
                            const float* __restrict__ Wd2, const float* __restrict__ bd2,
                            const float* __restrict__ Wo,  const float* __restrict__ bo,
                            float* __restrict__ out, int out_size) {
    __shared__ float g0[G2];
    __shared__ float g1s[L1];
    __shared__ float g2s[L2];
    int t = threadIdx.x;

    if (t < G2) {
        float p = 1.0f;
        for (int b = 0; b < PBLK; b++) p *= g_part[b * G2 + t];
        g0[t] = p;
    }
    __syncthreads();

    {
        float acc = bd1[t];
        #pragma unroll
        for (int k = 0; k < G2; k++) acc = fmaf(g0[k], Wd1[k * L1 + t], acc);
        g1s[t] = tanhf(acc);
    }
    __syncthreads();

    if (t < L2) {
        float acc = bd2[t];
        #pragma unroll
        for (int j = 0; j < L1; j++) acc = fmaf(g1s[j], Wd2[j * L2 + t], acc);
        float gv = tanhf(acc);
        g2s[t] = gv;
        if (1 + t < out_size) out[1 + t] = gv;
    }
    __syncthreads();

    if (t == 0) {
        float acc = bo[0];
        #pragma unroll
        for (int f2 = 0; f2 < L2; f2++) acc = fmaf(g2s[f2], Wo[f2], acc);
        out[0] = acc;
    }
}

// ---------------- launcher ----------------
extern "C" void kernel_launch(void* const* d_in, const int* in_sizes, int n_in,
                              void* d_out, int out_size) {
    const float* x   = (const float*)d_in[0];
    const int*   ei  = (const int*)d_in[1];     // int32 [2, E]
    const float* W1  = (const float*)d_in[2];
    const float* b1  = (const float*)d_in[3];
    const float* W2  = (const float*)d_in[4];
    const float* b2  = (const float*)d_in[5];
    const float* Wd1 = (const float*)d_in[6];
    const float* bd1 = (const float*)d_in[7];
    const float* Wd2 = (const float*)d_in[8];
    const float* bd2 = (const float*)d_in[9];
    const float* Wo  = (const float*)d_in[10];
    const float* bo  = (const float*)d_in[11];
    float* out = (float*)d_out;

    int n = in_sizes[0] / F_IN;       // 100000
    int E = in_sizes[1] / 2;          // 1600000

    const int MLP_SMEM = (F_IN * G1 + G1 + G1 * G2 + NB * XP + NB * G1) * 4; // 88576
    cudaFuncSetAttribute(mlp_kernel, cudaFuncAttributeMaxDynamicSharedMemorySize, MLP_SMEM);

    deg_init_kernel <<<(n + 255) / 256, 256>>>(n);
    deg_count_kernel<<<(E + 255) / 256, 256>>>(ei, E);

    // dinv + prescaled padded x + aggX self-loop init
    prep_kernel<<<((long long)n * XP + 255) / 256, 256>>>(x, n);

    // scatter layer 1 in 32-dim input space (8 lanes/edge)
    {
        long long lanes = (long long)E * 8;
        scatter1_kernel<<<(unsigned)((lanes + 255) / 256), 256>>>(ei, E);
    }

    // fused MLP: tanh(aggX@W1+b1) @ W2, pre-scale + self-loop init
    mlp_kernel<<<(n + NB - 1) / NB, 256, MLP_SMEM>>>(W1, b1, W2, n);

    // scatter layer 2 (16 lanes/edge)
    {
        long long lanes = (long long)E * 16;
        scatter2_kernel<<<(unsigned)((lanes + 255) / 256), 256>>>(ei, E);
    }

    prod_kernel<<<PBLK, 256>>>(b2, n);
    head_kernel<<<1, 128>>>(Wd1, bd1, Wd2, bd2, Wo, bo, out, out_size);
}

// round 5
// speedup vs baseline: 1.9118x; 1.1944x over previous
#include <cuda_runtime.h>
#include <cuda_bf16.h>
#include <math.h>

// ---------------- problem dims ----------------
#define N_MAX   100000
#define E_MAX   1600000
#define F_IN    28
#define XP      32      // padded input dim
#define G1      128
#define G2      64
#define L1      128
#define L2      64
#define PBLK    256
#define NB      64      // nodes per MLP block

// ---------------- scratch ----------------
__device__ __align__(16) int   g_cnt [N_MAX];      // in-degree (no self loop)
__device__ __align__(16) int   g_off [N_MAX];      // CSR offsets (exclusive scan)
__device__ __align__(16) int   g_cur [N_MAX];      // fill cursors
__device__ __align__(16) int   g_blk [512];        // scan block sums
__device__ __align__(16) int   g_srow[E_MAX];      // row ids sorted by col
__device__ __align__(16) float g_dinv[N_MAX];
__device__ __align__(16) float g_x32 [(size_t)N_MAX * XP];   // x * dinv[row], padded
__device__ __align__(16) float g_aggX[(size_t)N_MAX * XP];   // normalized layer-1 agg
__device__ __align__(16) float g_h2s [(size_t)N_MAX * G2];   // h2 * dinv[row]
__device__ __align__(16) float g_agg2[(size_t)N_MAX * G2];   // normalized layer-2 agg
__device__ __align__(16) float g_part[PBLK * G2];

// ---------------- degree histogram ----------------
__global__ void zero_cnt_kernel(int n) {
    int i = blockIdx.x * blockDim.x + threadIdx.x;
    if (i < n) g_cnt[i] = 0;
}

__global__ void deg_count_kernel(const int* __restrict__ ei, int E) {
    int e = blockIdx.x * blockDim.x + threadIdx.x;
    if (e < E) atomicAdd(&g_cnt[ei[E + e]], 1);
}

// ---------------- hierarchical exclusive scan over g_cnt ----------------
__global__ void scan1_kernel(int n) {      // 1024-thread blocks
    __shared__ int s[1024];
    int i = blockIdx.x * 1024 + threadIdx.x;
    int v = (i < n) ? g_cnt[i] : 0;
    s[threadIdx.x] = v;
    __syncthreads();
    for (int d = 1; d < 1024; d <<= 1) {
        int t = (threadIdx.x >= d) ? s[threadIdx.x - d] : 0;
        __syncthreads();
        s[threadIdx.x] += t;
        __syncthreads();
    }
    if (i < n) g_off[i] = s[threadIdx.x] - v;           // exclusive within block
    if (threadIdx.x == 1023) g_blk[blockIdx.x] = s[1023];
}

__global__ void scan2_kernel(int nb) {     // single block of 128
    __shared__ int s[128];
    int v = (threadIdx.x < nb) ? g_blk[threadIdx.x] : 0;
    s[threadIdx.x] = v;
    __syncthreads();
    for (int d = 1; d < 128; d <<= 1) {
        int t = (threadIdx.x >= d) ? s[threadIdx.x - d] : 0;
        __syncthreads();
        s[threadIdx.x] += t;
        __syncthreads();
    }
    if (threadIdx.x < nb) g_blk[threadIdx.x] = s[threadIdx.x] - v;  // exclusive
}

__global__ void scan3_kernel(int n) {
    int i = blockIdx.x * blockDim.x + threadIdx.x;
    if (i < n) {
        int o = g_off[i] + g_blk[i >> 10];
        g_off[i] = o;
        g_cur[i] = o;
    }
}

// ---------------- CSR fill: sorted_row[pos] = row, pos = cursor[col]++ ----------------
__global__ void fill_kernel(const int* __restrict__ ei, int E) {
    int e = blockIdx.x * blockDim.x + threadIdx.x;
    if (e < E) {
        int c = ei[E + e];
        int pos = atomicAdd(&g_cur[c], 1);
        g_srow[pos] = ei[e];
    }
}

// ---------------- prep: dinv + prescaled padded x ----------------
__global__ void prep_kernel(const float* __restrict__ x, int n) {
    int i = blockIdx.x * blockDim.x + threadIdx.x;
    if (i >= n * XP) return;
    int node = i >> 5, j = i & 31;
    float di = rsqrtf((float)(g_cnt[node] + 1));   // +1 self loop
    if (j == 0) g_dinv[node] = di;
    g_x32[i] = (j < F_IN) ? x[(size_t)node * F_IN + j] * di : 0.0f;
}

// ---------------- gather layer 1: warp per node, 32 floats ----------------
__global__ void gather1_kernel(int n) {
    int w    = (blockIdx.x * blockDim.x + threadIdx.x) >> 5;
    int lane = threadIdx.x & 31;
    if (w >= n) return;
    int beg = g_off[w], cnt = g_cnt[w];
    float acc = g_x32[(size_t)w * XP + lane];      // self loop
    int k = 0;
    for (; k + 2 <= cnt; k += 2) {
        int r0 = g_srow[beg + k];
        int r1 = g_srow[beg + k + 1];
        float a = g_x32[(size_t)r0 * XP + lane];
        float b = g_x32[(size_t)r1 * XP + lane];
        acc += a + b;
    }
    if (k < cnt)
        acc += g_x32[(size_t)g_srow[beg + k] * XP + lane];
    g_aggX[(size_t)w * XP + lane] = acc * g_dinv[w];
}

// ---------------- fused MLP: t = tanh(aggX@W1 + b1); h2s = (t@W2)*dinv ----------------
__global__ void mlp_kernel(const float* __restrict__ W1, const float* __restrict__ b1,
                           const float* __restrict__ W2, int n) {
    extern __shared__ float sm[];
    float* Ws1 = sm;                  // 28*128
    float* b1s = Ws1 + F_IN * G1;     // 128
    float* Ws2 = b1s + G1;            // 128*64
    float* xs  = Ws2 + G1 * G2;       // 64*32
    float* ts  = xs + NB * XP;        // 64*128

    int t = threadIdx.x;
    for (int i = t; i < F_IN * G1; i += 256) Ws1[i] = W1[i];
    if (t < G1) b1s[t] = b1[t];
    for (int i = t; i < G1 * G2; i += 256) Ws2[i] = W2[i];

    int base = blockIdx.x * NB;
    int cnt  = min(NB, n - base);
    for (int i = t; i < cnt * XP; i += 256)
        xs[i] = g_aggX[(size_t)base * XP + i];
    __syncthreads();

    {
        int f = t & 127, g = t >> 7;
        for (int nn = g; nn < cnt; nn += 2) {
            float acc = b1s[f];
            #pragma unroll
            for (int k = 0; k < F_IN; k++)
                acc = fmaf(xs[nn * XP + k], Ws1[k * G1 + f], acc);
            ts[nn * G1 + f] = tanhf(acc);
        }
    }
    __syncthreads();

    {
        int f = t & 63, g = t >> 6;
        for (int nn = g; nn < cnt; nn += 4) {
            float acc = 0.f;
            #pragma unroll
            for (int k = 0; k < G1; k++)
                acc = fmaf(ts[nn * G1 + k], Ws2[k * G2 + f], acc);
            int node = base + nn;
            g_h2s[(size_t)node * G2 + f] = acc * g_dinv[node];
        }
    }
}

// ---------------- gather layer 2: warp per node, 64 floats (2 per lane) ----------------
__global__ void gather2_kernel(int n) {
    int w    = (blockIdx.x * blockDim.x + threadIdx.x) >> 5;
    int lane = threadIdx.x & 31;
    if (w >= n) return;
    int beg = g_off[w], cnt = g_cnt[w];
    size_t self = (size_t)w * G2;
    float acc0 = g_h2s[self + lane];           // self loop
    float acc1 = g_h2s[self + lane + 32];
    int k = 0;
    for (; k + 2 <= cnt; k += 2) {
        size_t r0 = (size_t)g_srow[beg + k] * G2;
        size_t r1 = (size_t)g_srow[beg + k + 1] * G2;
        float a0 = g_h2s[r0 + lane];
        float a1 = g_h2s[r0 + lane + 32];
        float b0 = g_h2s[r1 + lane];
        float b1 = g_h2s[r1 + lane + 32];
        acc0 += a0 + b0;
        acc1 += a1 + b1;
    }
    if (k < cnt) {
        size_t r0 = (size_t)g_srow[beg + k] * G2;
        acc0 += g_h2s[r0 + lane];
        acc1 += g_h2s[r0 + lane + 32];
    }
    float dc = g_dinv[w];
    g_agg2[self + lane]      = acc0 * dc;
    g_agg2[self + lane + 32] = acc1 * dc;
}

// ---------------- product pooling partials ----------------
__global__ void prod_kernel(const float* __restrict__ b2, int n) {
    __shared__ float s[4][G2];
    int f   = threadIdx.x & 63;
    int grp = threadIdx.x >> 6;
    float b = b2[f];
    float p = 1.0f;
    for (int i = blockIdx.x * 4 + grp; i < n; i += gridDim.x * 4)
        p *= tanhf(g_agg2[(size_t)i * G2 + f] + b);
    s[grp][f] = p;
    __syncthreads();
    if (grp == 0)
        g_part[blockIdx.x * G2 + f] = s[0][f] * s[1][f] * s[2][f] * s[3][f];
}

// ---------------- final head ----------------
__global__ void head_kernel(const float* __restrict__ Wd1, const float* __restrict__ bd1,
                            const float* __restrict__ Wd2, const float* __restrict__ bd2,
                            const float* __restrict__ Wo,  const float* __restrict__ bo,
                            float* __restrict__ out, int out_size) {
    __shared__ float g0[G2];
    __shared__ float g1s[L1];
    __shared__ float g2s[L2];
    int t = threadIdx.x;

    if (t < G2) {
        float p = 1.0f;
        for (int b = 0; b < PBLK; b++) p *= g_part[b * G2 + t];
        g0[t] = p;
    }
    __syncthreads();

    {
        float acc = bd1[t];
        #pragma unroll
        for (int k = 0; k < G2; k++) acc = fmaf(g0[k], Wd1[k * L1 + t], acc);
        g1s[t] = tanhf(acc);
    }
    __syncthreads();

    if (t < L2) {
        float acc = bd2[t];
        #pragma unroll
        for (int j = 0; j < L1; j++) acc = fmaf(g1s[j], Wd2[j * L2 + t], acc);
        float gv = tanhf(acc);
        g2s[t] = gv;
        if (1 + t < out_size) out[1 + t] = gv;
    }
    __syncthreads();

    if (t == 0) {
        float acc = bo[0];
        #pragma unroll
        for (int f2 = 0; f2 < L2; f2++) acc = fmaf(g2s[f2], Wo[f2], acc);
        out[0] = acc;
    }
}

// ---------------- launcher ----------------
extern "C" void kernel_launch(void* const* d_in, const int* in_sizes, int n_in,
                              void* d_out, int out_size) {
    const float* x   = (const float*)d_in[0];
    const int*   ei  = (const int*)d_in[1];     // int32 [2, E]
    const float* W1  = (const float*)d_in[2];
    const float* b1  = (const float*)d_in[3];
    const float* W2  = (const float*)d_in[4];
    const float* b2  = (const float*)d_in[5];
    const float* Wd1 = (const float*)d_in[6];
    const float* bd1 = (const float*)d_in[7];
    const float* Wd2 = (const float*)d_in[8];
    const float* bd2 = (const float*)d_in[9];
    const float* Wo  = (const float*)d_in[10];
    const float* bo  = (const float*)d_in[11];
    float* out = (float*)d_out;

    int n = in_sizes[0] / F_IN;       // 100000
    int E = in_sizes[1] / 2;          // 1600000
    int nb = (n + 1023) >> 10;        // scan blocks (98)

    const int MLP_SMEM = (F_IN * G1 + G1 + G1 * G2 + NB * XP + NB * G1) * 4; // 88576
    cudaFuncSetAttribute(mlp_kernel, cudaFuncAttributeMaxDynamicSharedMemorySize, MLP_SMEM);

    // CSR build
    zero_cnt_kernel <<<(n + 255) / 256, 256>>>(n);
    deg_count_kernel<<<(E + 255) / 256, 256>>>(ei, E);
    scan1_kernel    <<<nb, 1024>>>(n);
    scan2_kernel    <<<1, 128>>>(nb);
    scan3_kernel    <<<(n + 255) / 256, 256>>>(n);
    fill_kernel     <<<(E + 255) / 256, 256>>>(ei, E);

    // node prep
    prep_kernel<<<((long long)n * XP + 255) / 256, 256>>>(x, n);

    // layer-1 aggregation in 32-dim input space (warp/node gather)
    gather1_kernel<<<(n * 32 + 255) / 256, 256>>>(n);

    // fused MLP
    mlp_kernel<<<(n + NB - 1) / NB, 256, MLP_SMEM>>>(W1, b1, W2, n);

    // layer-2 aggregation (warp/node gather)
    gather2_kernel<<<(n * 32 + 255) / 256, 256>>>(n);

    // pooling + head
    prod_kernel<<<PBLK, 256>>>(b2, n);
    head_kernel<<<1, 128>>>(Wd1, bd1, Wd2, bd2, Wo, bo, out, out_size);
}

// round 6
// speedup vs baseline: 2.6930x; 1.4086x over previous
#include <cuda_runtime.h>
#include <cuda_bf16.h>
#include <math.h>

// ---------------- problem dims ----------------
#define N_MAX   100000
#define E_MAX   1600000
#define F_IN    28
#define XPH     16      // padded input dim in bf162 pairs (32 bf16)
#define G1      128
#define G2      64
#define L1      128
#define L2      64
#define PBLK    256
#define NB      64      // nodes per MLP block

// ---------------- scratch ----------------
__device__ __align__(16) int   g_cnt [N_MAX];
__device__ __align__(16) int   g_off [N_MAX];
__device__ __align__(16) int   g_cur [N_MAX];
__device__ __align__(16) int   g_blk [512];
__device__ __align__(16) int   g_srow[E_MAX];
__device__ __align__(16) float g_dinv[N_MAX];
__device__ __align__(16) __nv_bfloat162 g_x32b [(size_t)N_MAX * XPH];  // x*dinv, padded 32 bf16
__device__ __align__(16) __nv_bfloat162 g_aggXb[(size_t)N_MAX * XPH];  // layer-1 agg (bf16)
__device__ __align__(16) __nv_bfloat162 g_h2sb [(size_t)N_MAX * (G2/2)]; // h2*dinv (bf16)
__device__ __align__(16) float g_agg2[(size_t)N_MAX * G2];             // layer-2 agg (fp32)
__device__ __align__(16) float g_part[PBLK * G2];

// ---------------- degree histogram ----------------
__global__ void zero_cnt_kernel(int n) {
    int i = blockIdx.x * blockDim.x + threadIdx.x;
    if (i < n) g_cnt[i] = 0;
}

__global__ void deg_count_kernel(const int* __restrict__ ei, int E) {
    int e = blockIdx.x * blockDim.x + threadIdx.x;
    if (e < E) atomicAdd(&g_cnt[ei[E + e]], 1);
}

// ---------------- hierarchical exclusive scan ----------------
__global__ void scan1_kernel(int n) {
    __shared__ int s[1024];
    int i = blockIdx.x * 1024 + threadIdx.x;
    int v = (i < n) ? g_cnt[i] : 0;
    s[threadIdx.x] = v;
    __syncthreads();
    for (int d = 1; d < 1024; d <<= 1) {
        int t = (threadIdx.x >= d) ? s[threadIdx.x - d] : 0;
        __syncthreads();
        s[threadIdx.x] += t;
        __syncthreads();
    }
    if (i < n) g_off[i] = s[threadIdx.x] - v;
    if (threadIdx.x == 1023) g_blk[blockIdx.x] = s[1023];
}

__global__ void scan2_kernel(int nb) {
    __shared__ int s[128];
    int v = (threadIdx.x < nb) ? g_blk[threadIdx.x] : 0;
    s[threadIdx.x] = v;
    __syncthreads();
    for (int d = 1; d < 128; d <<= 1) {
        int t = (threadIdx.x >= d) ? s[threadIdx.x - d] : 0;
        __syncthreads();
        s[threadIdx.x] += t;
        __syncthreads();
    }
    if (threadIdx.x < nb) g_blk[threadIdx.x] = s[threadIdx.x] - v;
}

__global__ void scan3_kernel(int n) {
    int i = blockIdx.x * blockDim.x + threadIdx.x;
    if (i < n) {
        int o = g_off[i] + g_blk[i >> 10];
        g_off[i] = o;
        g_cur[i] = o;
    }
}

__global__ void fill_kernel(const int* __restrict__ ei, int E) {
    int e = blockIdx.x * blockDim.x + threadIdx.x;
    if (e < E) {
        int c = ei[E + e];
        int pos = atomicAdd(&g_cur[c], 1);
        g_srow[pos] = ei[e];
    }
}

// ---------------- prep: dinv + prescaled padded x (bf16) ----------------
__global__ void prep_kernel(const float* __restrict__ x, int n) {
    int i = blockIdx.x * blockDim.x + threadIdx.x;
    if (i >= n * XPH) return;
    int node = i >> 4, j = i & 15;
    float di = rsqrtf((float)(g_cnt[node] + 1));
    if (j == 0) g_dinv[node] = di;
    int k0 = 2 * j, k1 = 2 * j + 1;
    float v0 = (k0 < F_IN) ? x[(size_t)node * F_IN + k0] * di : 0.0f;
    float v1 = (k1 < F_IN) ? x[(size_t)node * F_IN + k1] * di : 0.0f;
    g_x32b[i] = __floats2bfloat162_rn(v0, v1);
}

// ---------------- gather layer 1: half-warp per node, bf162 per lane ----------------
__global__ void gather1_kernel(int n) {
    int t = blockIdx.x * blockDim.x + threadIdx.x;
    int w = t >> 4, lane = t & 15;
    if (w >= n) return;
    int beg = g_off[w], cnt = g_cnt[w];
    float2 acc = __bfloat1622float2(g_x32b[(size_t)w * XPH + lane]);  // self loop
    int k = 0;
    for (; k + 4 <= cnt; k += 4) {
        int r0 = g_srow[beg + k],     r1 = g_srow[beg + k + 1];
        int r2 = g_srow[beg + k + 2], r3 = g_srow[beg + k + 3];
        float2 a = __bfloat1622float2(g_x32b[(size_t)r0 * XPH + lane]);
        float2 b = __bfloat1622float2(g_x32b[(size_t)r1 * XPH + lane]);
        float2 c = __bfloat1622float2(g_x32b[(size_t)r2 * XPH + lane]);
        float2 d = __bfloat1622float2(g_x32b[(size_t)r3 * XPH + lane]);
        acc.x += (a.x + b.x) + (c.x + d.x);
        acc.y += (a.y + b.y) + (c.y + d.y);
    }
    for (; k < cnt; k++) {
        float2 a = __bfloat1622float2(g_x32b[(size_t)g_srow[beg + k] * XPH + lane]);
        acc.x += a.x; acc.y += a.y;
    }
    float dc = g_dinv[w];
    g_aggXb[(size_t)w * XPH + lane] = __floats2bfloat162_rn(acc.x * dc, acc.y * dc);
}

// ---------------- fused MLP (bf16 HFMA2): t = tanh(aggX@W1+b1); h2s=(t@W2)*dinv ----------------
__global__ void mlp_kernel(const float* __restrict__ W1, const float* __restrict__ b1,
                           const float* __restrict__ W2, int n) {
    __shared__ __nv_bfloat162 W1p[(F_IN/2) * G1];   // 14*128 pairs = 7 KB
    __shared__ float          b1s[G1];
    __shared__ __nv_bfloat162 W2p[(G1/2) * G2];     // 64*64 pairs = 16 KB
    __shared__ __nv_bfloat162 xs[NB * XPH];         // 4 KB
    __shared__ __nv_bfloat16  ts[NB * G1];          // 16 KB

    int t = threadIdx.x;
    // pack W1 along k-pairs: W1p[p*G1+f] = (W1[2p][f], W1[2p+1][f])
    for (int i = t; i < (F_IN/2) * G1; i += 256) {
        int p = i / G1, f = i % G1;
        W1p[i] = __floats2bfloat162_rn(W1[(2*p) * G1 + f], W1[(2*p+1) * G1 + f]);
    }
    if (t < G1) b1s[t] = b1[t];
    for (int i = t; i < (G1/2) * G2; i += 256) {
        int p = i / G2, f = i % G2;
        W2p[i] = __floats2bfloat162_rn(W2[(2*p) * G2 + f], W2[(2*p+1) * G2 + f]);
    }

    int base = blockIdx.x * NB;
    int cnt  = min(NB, n - base);
    for (int i = t; i < cnt * XPH; i += 256)
        xs[i] = g_aggXb[(size_t)base * XPH + i];
    __syncthreads();

    // stage 1: 128 features x 2 node groups
    {
        int f = t & 127, g = t >> 7;
        for (int nn = g; nn < cnt; nn += 2) {
            __nv_bfloat162 acc2 = __floats2bfloat162_rn(0.f, 0.f);
            #pragma unroll
            for (int p = 0; p < F_IN/2; p++)
                acc2 = __hfma2(xs[nn * XPH + p], W1p[p * G1 + f], acc2);
            float s = __low2float(acc2) + __high2float(acc2) + b1s[f];
            ts[nn * G1 + f] = __float2bfloat16(tanhf(s));
        }
    }
    __syncthreads();

    // stage 2: 64 features x 4 node groups
    {
        int f = t & 63, g = t >> 6;
        for (int nn = g; nn < cnt; nn += 4) {
            const __nv_bfloat162* tp = reinterpret_cast<const __nv_bfloat162*>(ts + nn * G1);
            __nv_bfloat162 acc2 = __floats2bfloat162_rn(0.f, 0.f);
            #pragma unroll
            for (int p = 0; p < G1/2; p++)
                acc2 = __hfma2(tp[p], W2p[p * G2 + f], acc2);
            float h2 = __low2float(acc2) + __high2float(acc2);
            int node = base + nn;
            reinterpret_cast<__nv_bfloat16*>(g_h2sb)[(size_t)node * G2 + f] =
                __float2bfloat16(h2 * g_dinv[node]);
        }
    }
}

// ---------------- gather layer 2: warp per node, bf162 per lane (64 bf16 row) ----------------
__global__ void gather2_kernel(int n) {
    int t = blockIdx.x * blockDim.x + threadIdx.x;
    int w = t >> 5, lane = t & 31;
    if (w >= n) return;
    int beg = g_off[w], cnt = g_cnt[w];
    float2 acc = __bfloat1622float2(g_h2sb[(size_t)w * 32 + lane]);  // self loop
    int k = 0;
    for (; k + 4 <= cnt; k += 4) {
        int r0 = g_srow[beg + k],     r1 = g_srow[beg + k + 1];
        int r2 = g_srow[beg + k + 2], r3 = g_srow[beg + k + 3];
        float2 a = __bfloat1622float2(g_h2sb[(size_t)r0 * 32 + lane]);
        float2 b = __bfloat1622float2(g_h2sb[(size_t)r1 * 32 + lane]);
        float2 c = __bfloat1622float2(g_h2sb[(size_t)r2 * 32 + lane]);
        float2 d = __bfloat1622float2(g_h2sb[(size_t)r3 * 32 + lane]);
        acc.x += (a.x + b.x) + (c.x + d.x);
        acc.y += (a.y + b.y) + (c.y + d.y);
    }
    for (; k < cnt; k++) {
        float2 a = __bfloat1622float2(g_h2sb[(size_t)g_srow[beg + k] * 32 + lane]);
        acc.x += a.x; acc.y += a.y;
    }
    float dc = g_dinv[w];
    float2 o; o.x = acc.x * dc; o.y = acc.y * dc;
    reinterpret_cast<float2*>(g_agg2)[(size_t)w * 32 + lane] = o;
}

// ---------------- product pooling partials ----------------
__global__ void prod_kernel(const float* __restrict__ b2, int n) {
    __shared__ float s[4][G2];
    int f   = threadIdx.x & 63;
    int grp = threadIdx.x >> 6;
    float b = b2[f];
    float p = 1.0f;
    for (int i = blockIdx.x * 4 + grp; i < n; i += gridDim.x * 4)
        p *= tanhf(g_agg2[(size_t)i * G2 + f] + b);
    s[grp][f] = p;
    __syncthreads();
    if (grp == 0)
        g_part[blockIdx.x * G2 + f] = s[0][f] * s[1][f] * s[2][f] * s[3][f];
}

// ---------------- final head (exact fp32) ----------------
__global__ void head_kernel(const float* __restrict__ Wd1, const float* __restrict__ bd1,
                            const float* __restrict__ Wd2, const float* __restrict__ bd2,
                            const float* __restrict__ Wo,  const float* __restrict__ bo,
                            float* __restrict__ out, int out_size) {
    __shared__ float g0[G2];
    __shared__ float g1s[L1];
    __shared__ float g2s[L2];
    int t = threadIdx.x;

    if (t < G2) {
        float p = 1.0f;
        for (int b = 0; b < PBLK; b++) p *= g_part[b * G2 + t];
        g0[t] = p;
    }
    __syncthreads();

    {
        float acc = bd1[t];
        #pragma unroll
        for (int k = 0; k < G2; k++) acc = fmaf(g0[k], Wd1[k * L1 + t], acc);
        g1s[t] = tanhf(acc);
    }
    __syncthreads();

    if (t < L2) {
        float acc = bd2[t];
        #pragma unroll
        for (int j = 0; j < L1; j++) acc = fmaf(g1s[j], Wd2[j * L2 + t], acc);
        float gv = tanhf(acc);
        g2s[t] = gv;
        if (1 + t < out_size) out[1 + t] = gv;
    }
    __syncthreads();

    if (t == 0) {
        float acc = bo[0];
        #pragma unroll
        for (int f2 = 0; f2 < L2; f2++) acc = fmaf(g2s[f2], Wo[f2], acc);
        out[0] = acc;
    }
}

// ---------------- launcher ----------------
extern "C" void kernel_launch(void* const* d_in, const int* in_sizes, int n_in,
                              void* d_out, int out_size) {
    const float* x   = (const float*)d_in[0];
    const int*   ei  = (const int*)d_in[1];
    const float* W1  = (const float*)d_in[2];
    const float* b1  = (const float*)d_in[3];
    const float* W2  = (const float*)d_in[4];
    const float* b2  = (const float*)d_in[5];
    const float* Wd1 = (const float*)d_in[6];
    const float* bd1 = (const float*)d_in[7];
    const float* Wd2 = (const float*)d_in[8];
    const float* bd2 = (const float*)d_in[9];
    const float* Wo  = (const float*)d_in[10];
    const float* bo  = (const float*)d_in[11];
    float* out = (float*)d_out;

    int n = in_sizes[0] / F_IN;       // 100000
    int E = in_sizes[1] / 2;          // 1600000
    int nb = (n + 1023) >> 10;

    // CSR build
    zero_cnt_kernel <<<(n + 255) / 256, 256>>>(n);
    deg_count_kernel<<<(E + 255) / 256, 256>>>(ei, E);
    scan1_kernel    <<<nb, 1024>>>(n);
    scan2_kernel    <<<1, 128>>>(nb);
    scan3_kernel    <<<(n + 255) / 256, 256>>>(n);
    fill_kernel     <<<(E + 255) / 256, 256>>>(ei, E);

    // node prep (bf16 prescaled x)
    prep_kernel<<<((long long)n * XPH + 255) / 256, 256>>>(x, n);

    // layer-1 aggregation (half-warp per node)
    gather1_kernel<<<((long long)n * 16 + 255) / 256, 256>>>(n);

    // fused bf16 MLP
    mlp_kernel<<<(n + NB - 1) / NB, 256>>>(W1, b1, W2, n);

    // layer-2 aggregation (warp per node)
    gather2_kernel<<<((long long)n * 32 + 255) / 256, 256>>>(n);

    // pooling + head
    prod_kernel<<<PBLK, 256>>>(b2, n);
    head_kernel<<<1, 128>>>(Wd1, bd1, Wd2, bd2, Wo, bo, out, out_size);
}

// round 7
// speedup vs baseline: 2.7221x; 1.0108x over previous
#include <cuda_runtime.h>
#include <cuda_bf16.h>
#include <math.h>

// ---------------- problem dims ----------------
#define N_MAX   100000
#define E_MAX   1600000
#define F_IN    28
#define XPH     16      // padded input dim in bf162 pairs (32 bf16)
#define G1      128
#define G2      64
#define L1      128
#define L2      64
#define NB      64      // nodes per MLP block
#define GPB     1024    // gather2prod blocks

// ---------------- scratch ----------------
__device__ __align__(16) int   g_cnt [N_MAX];
__device__ __align__(16) int   g_off [N_MAX];
__device__ __align__(16) int   g_cur [N_MAX];
__device__ __align__(16) int   g_blk [512];
__device__ __align__(16) int   g_srow[E_MAX];
__device__ __align__(16) float g_dinv[N_MAX];
__device__ __align__(16) __nv_bfloat162 g_x32b [(size_t)N_MAX * XPH];    // x*dinv (bf16, padded 32)
__device__ __align__(16) __nv_bfloat162 g_aggXb[(size_t)N_MAX * XPH];    // layer-1 agg (bf16)
__device__ __align__(16) __nv_bfloat162 g_h2sb [(size_t)N_MAX * (G2/2)]; // h2*dinv (bf16)
__device__ __align__(16) float g_part[GPB * G2];

// ---------------- degree histogram ----------------
__global__ void zero_cnt_kernel(int n) {
    int i = blockIdx.x * blockDim.x + threadIdx.x;
    if (i < n) g_cnt[i] = 0;
}

__global__ void deg_count_kernel(const int* __restrict__ ei, int E) {
    int e = blockIdx.x * blockDim.x + threadIdx.x;
    if (e < E) atomicAdd(&g_cnt[ei[E + e]], 1);
}

// ---------------- scan1: per-1024-block exclusive scan (shfl) ----------------
__global__ void scan1_kernel(int n) {
    __shared__ int wsum[32];
    int i = blockIdx.x * 1024 + threadIdx.x;
    int v = (i < n) ? g_cnt[i] : 0;
    int lane = threadIdx.x & 31, wid = threadIdx.x >> 5;
    int x = v;
    #pragma unroll
    for (int d = 1; d < 32; d <<= 1) {
        int t = __shfl_up_sync(0xFFFFFFFFu, x, d);
        if (lane >= d) x += t;
    }
    if (lane == 31) wsum[wid] = x;
    __syncthreads();
    if (wid == 0) {
        int y = wsum[lane];
        #pragma unroll
        for (int d = 1; d < 32; d <<= 1) {
            int t = __shfl_up_sync(0xFFFFFFFFu, y, d);
            if (lane >= d) y += t;
        }
        wsum[lane] = y;
    }
    __syncthreads();
    int off = x - v + (wid > 0 ? wsum[wid - 1] : 0);   // exclusive within block
    if (i < n) g_off[i] = off;
    if (threadIdx.x == 1023) g_blk[blockIdx.x] = off + v;   // block total
}

// ---------------- fused: scan of block sums (redundant per block) + global off/cur
//                  + dinv + prescaled padded x (bf16). one thread per (node, j<16) ----------------
__global__ void scan23_prep_kernel(const float* __restrict__ x, int n, int nb) {
    __shared__ int s[128];
    int t = threadIdx.x;
    if (t < 128) s[t] = (t < nb) ? g_blk[t] : 0;
    __syncthreads();
    // inclusive Hillis-Steele over 128 (only first 128 threads participate)
    for (int d = 1; d < 128; d <<= 1) {
        int v = 0;
        if (t < 128 && t >= d) v = s[t - d];
        __syncthreads();
        if (t < 128) s[t] += v;
        __syncthreads();
    }

    int i = blockIdx.x * blockDim.x + threadIdx.x;
    if (i >= n * XPH) return;
    int node = i >> 4, j = i & 15;
    float di = rsqrtf((float)(g_cnt[node] + 1));
    if (j == 0) {
        g_dinv[node] = di;
        int blk = node >> 10;
        int o = g_off[node] + (blk > 0 ? s[blk - 1] : 0);   // exclusive block offset
        g_off[node] = o;
        g_cur[node] = o;
    }
    int k0 = 2 * j, k1 = 2 * j + 1;
    float v0 = (k0 < F_IN) ? x[(size_t)node * F_IN + k0] * di : 0.0f;
    float v1 = (k1 < F_IN) ? x[(size_t)node * F_IN + k1] * di : 0.0f;
    g_x32b[i] = __floats2bfloat162_rn(v0, v1);
}

// ---------------- CSR fill ----------------
__global__ void fill_kernel(const int* __restrict__ ei, int E) {
    int e = blockIdx.x * blockDim.x + threadIdx.x;
    if (e < E) {
        int c = ei[E + e];
        int pos = atomicAdd(&g_cur[c], 1);
        g_srow[pos] = ei[e];
    }
}

// ---------------- gather layer 1: half-warp per node, bf162 per lane ----------------
__global__ void gather1_kernel(int n) {
    int t = blockIdx.x * blockDim.x + threadIdx.x;
    int w = t >> 4, lane = t & 15;
    if (w >= n) return;
    int beg = g_off[w], cnt = g_cnt[w];
    float2 acc = __bfloat1622float2(g_x32b[(size_t)w * XPH + lane]);  // self loop
    int k = 0;
    for (; k + 4 <= cnt; k += 4) {
        int r0 = g_srow[beg + k],     r1 = g_srow[beg + k + 1];
        int r2 = g_srow[beg + k + 2], r3 = g_srow[beg + k + 3];
        float2 a = __bfloat1622float2(g_x32b[(size_t)r0 * XPH + lane]);
        float2 b = __bfloat1622float2(g_x32b[(size_t)r1 * XPH + lane]);
        float2 c = __bfloat1622float2(g_x32b[(size_t)r2 * XPH + lane]);
        float2 d = __bfloat1622float2(g_x32b[(size_t)r3 * XPH + lane]);
        acc.x += (a.x + b.x) + (c.x + d.x);
        acc.y += (a.y + b.y) + (c.y + d.y);
    }
    for (; k < cnt; k++) {
        float2 a = __bfloat1622float2(g_x32b[(size_t)g_srow[beg + k] * XPH + lane]);
        acc.x += a.x; acc.y += a.y;
    }
    float dc = g_dinv[w];
    g_aggXb[(size_t)w * XPH + lane] = __floats2bfloat162_rn(acc.x * dc, acc.y * dc);
}

// ---------------- fused MLP (bf16 HFMA2) ----------------
__global__ void mlp_kernel(const float* __restrict__ W1, const float* __restrict__ b1,
                           const float* __restrict__ W2, int n) {
    __shared__ __nv_bfloat162 W1p[(F_IN/2) * G1];
    __shared__ float          b1s[G1];
    __shared__ __nv_bfloat162 W2p[(G1/2) * G2];
    __shared__ __nv_bfloat162 xs[NB * XPH];
    __shared__ __nv_bfloat16  ts[NB * G1];

    int t = threadIdx.x;
    for (int i = t; i < (F_IN/2) * G1; i += 256) {
        int p = i / G1, f = i % G1;
        W1p[i] = __floats2bfloat162_rn(W1[(2*p) * G1 + f], W1[(2*p+1) * G1 + f]);
    }
    if (t < G1) b1s[t] = b1[t];
    for (int i = t; i < (G1/2) * G2; i += 256) {
        int p = i / G2, f = i % G2;
        W2p[i] = __floats2bfloat162_rn(W2[(2*p) * G2 + f], W2[(2*p+1) * G2 + f]);
    }

    int base = blockIdx.x * NB;
    int cnt  = min(NB, n - base);
    for (int i = t; i < cnt * XPH; i += 256)
        xs[i] = g_aggXb[(size_t)base * XPH + i];
    __syncthreads();

    {
        int f = t & 127, g = t >> 7;
        for (int nn = g; nn < cnt; nn += 2) {
            __nv_bfloat162 acc2 = __floats2bfloat162_rn(0.f, 0.f);
            #pragma unroll
            for (int p = 0; p < F_IN/2; p++)
                acc2 = __hfma2(xs[nn * XPH + p], W1p[p * G1 + f], acc2);
            float s = __low2float(acc2) + __high2float(acc2) + b1s[f];
            ts[nn * G1 + f] = __float2bfloat16(tanhf(s));
        }
    }
    __syncthreads();

    {
        int f = t & 63, g = t >> 6;
        for (int nn = g; nn < cnt; nn += 4) {
            const __nv_bfloat162* tp = reinterpret_cast<const __nv_bfloat162*>(ts + nn * G1);
            __nv_bfloat162 acc2 = __floats2bfloat162_rn(0.f, 0.f);
            #pragma unroll
            for (int p = 0; p < G1/2; p++)
                acc2 = __hfma2(tp[p], W2p[p * G2 + f], acc2);
            float h2 = __low2float(acc2) + __high2float(acc2);
            int node = base + nn;
            reinterpret_cast<__nv_bfloat16*>(g_h2sb)[(size_t)node * G2 + f] =
                __float2bfloat16(h2 * g_dinv[node]);
        }
    }
}

// ---------------- fused gather layer 2 + tanh + product pooling ----------------
// warp per node (strided); per-lane running product of 2 features; block combine.
__global__ void gather2prod_kernel(const float* __restrict__ b2, int n) {
    __shared__ float sp[8][G2];
    int lane = threadIdx.x & 31, wid = threadIdx.x >> 5;
    int gw = blockIdx.x * 8 + wid;
    int nw = gridDim.x * 8;
    float2 bb = reinterpret_cast<const float2*>(b2)[lane];
    float p0 = 1.f, p1 = 1.f;

    for (int w = gw; w < n; w += nw) {
        int beg = g_off[w], cnt = g_cnt[w];
        float2 acc = __bfloat1622float2(g_h2sb[(size_t)w * 32 + lane]);  // self loop
        int k = 0;
        for (; k + 4 <= cnt; k += 4) {
            int r0 = g_srow[beg + k],     r1 = g_srow[beg + k + 1];
            int r2 = g_srow[beg + k + 2], r3 = g_srow[beg + k + 3];
            float2 a = __bfloat1622float2(g_h2sb[(size_t)r0 * 32 + lane]);
            float2 b = __bfloat1622float2(g_h2sb[(size_t)r1 * 32 + lane]);
            float2 c = __bfloat1622float2(g_h2sb[(size_t)r2 * 32 + lane]);
            float2 d = __bfloat1622float2(g_h2sb[(size_t)r3 * 32 + lane]);
            acc.x += (a.x + b.x) + (c.x + d.x);
            acc.y += (a.y + b.y) + (c.y + d.y);
        }
        for (; k < cnt; k++) {
            float2 a = __bfloat1622float2(g_h2sb[(size_t)g_srow[beg + k] * 32 + lane]);
            acc.x += a.x; acc.y += a.y;
        }
        float dc = g_dinv[w];
        p0 *= tanhf(fmaf(acc.x, dc, bb.x));
        p1 *= tanhf(fmaf(acc.y, dc, bb.y));
    }

    sp[wid][2 * lane]     = p0;
    sp[wid][2 * lane + 1] = p1;
    __syncthreads();
    int t = threadIdx.x;
    if (t < G2) {
        float p = sp[0][t];
        #pragma unroll
        for (int k = 1; k < 8; k++) p *= sp[k][t];
        g_part[blockIdx.x * G2 + t] = p;
    }
}

// ---------------- final head (exact fp32) ----------------
__global__ void head_kernel(const float* __restrict__ Wd1, const float* __restrict__ bd1,
                            const float* __restrict__ Wd2, const float* __restrict__ bd2,
                            const float* __restrict__ Wo,  const float* __restrict__ bo,
                            float* __restrict__ out, int out_size) {
    __shared__ float g0[G2];
    __shared__ float g1s[L1];
    __shared__ float g2s[L2];
    int t = threadIdx.x;

    if (t < G2) {
        float p0 = 1.f, p1 = 1.f, p2 = 1.f, p3 = 1.f;
        for (int b = 0; b < GPB; b += 4) {
            p0 *= g_part[(b + 0) * G2 + t];
            p1 *= g_part[(b + 1) * G2 + t];
            p2 *= g_part[(b + 2) * G2 + t];
            p3 *= g_part[(b + 3) * G2 + t];
        }
        g0[t] = (p0 * p1) * (p2 * p3);
    }
    __syncthreads();

    {
        float acc = bd1[t];
        #pragma unroll
        for (int k = 0; k < G2; k++) acc = fmaf(g0[k], Wd1[k * L1 + t], acc);
        g1s[t] = tanhf(acc);
    }
    __syncthreads();

    if (t < L2) {
        float acc = bd2[t];
        #pragma unroll
        for (int j = 0; j < L1; j++) acc = fmaf(g1s[j], Wd2[j * L2 + t], acc);
        float gv = tanhf(acc);
        g2s[t] = gv;
        if (1 + t < out_size) out[1 + t] = gv;
    }
    __syncthreads();

    if (t == 0) {
        float acc = bo[0];
        #pragma unroll
        for (int f2 = 0; f2 < L2; f2++) acc = fmaf(g2s[f2], Wo[f2], acc);
        out[0] = acc;
    }
}

// ---------------- launcher ----------------
extern "C" void kernel_launch(void* const* d_in, const int* in_sizes, int n_in,
                              void* d_out, int out_size) {
    const float* x   = (const float*)d_in[0];
    const int*   ei  = (const int*)d_in[1];
    const float* W1  = (const float*)d_in[2];
    const float* b1  = (const float*)d_in[3];
    const float* W2  = (const float*)d_in[4];
    const float* b2  = (const float*)d_in[5];
    const float* Wd1 = (const float*)d_in[6];
    const float* bd1 = (const float*)d_in[7];
    const float* Wd2 = (const float*)d_in[8];
    const float* bd2 = (const float*)d_in[9];
    const float* Wo  = (const float*)d_in[10];
    const float* bo  = (const float*)d_in[11];
    float* out = (float*)d_out;

    int n = in_sizes[0] / F_IN;       // 100000
    int E = in_sizes[1] / 2;          // 1600000
    int nb = (n + 1023) >> 10;        // 98

    zero_cnt_kernel  <<<(n + 255) / 256, 256>>>(n);
    deg_count_kernel <<<(E + 255) / 256, 256>>>(ei, E);
    scan1_kernel     <<<nb, 1024>>>(n);
    scan23_prep_kernel<<<((long long)n * XPH + 255) / 256, 256>>>(x, n, nb);
    fill_kernel      <<<(E + 255) / 256, 256>>>(ei, E);
    gather1_kernel   <<<((long long)n * 16 + 255) / 256, 256>>>(n);
    mlp_kernel       <<<(n + NB - 1) / NB, 256>>>(W1, b1, W2, n);
    gather2prod_kernel<<<GPB, 256>>>(b2, n);
    head_kernel      <<<1, 128>>>(Wd1, bd1, Wd2, bd2, Wo, bo, out, out_size);
}